// round 1
// baseline (speedup 1.0000x reference)
#include <cuda_runtime.h>
#include <stdint.h>

// Problem constants (fixed shapes per reference):
//   x:        (B, M, N)  float32
//   location: (B, M, 2)  int64 (or int32 if JAX x64 disabled) -- (y, x) pairs
//   out:      (B, N, H, W) float32, H=W=128
#define BB   32
#define MM   512
#define NN   128
#define WPX  128
#define HWPX 16384   // 128*128
#define HW4  4096    // HWPX / 4

// Inverse map: inv[b*HWPX + pixel] = m (entity index) or -1 if empty. 2 MB.
__device__ int g_inv[BB * HWPX];

// ---------------------------------------------------------------------------
// Kernel 1: init inverse map to -1 (vectorized int4 stores).
// grid: BB*HWPX/4 threads total.
__global__ void init_inv_kernel() {
    int i = blockIdx.x * blockDim.x + threadIdx.x;
    ((int4*)g_inv)[i] = make_int4(-1, -1, -1, -1);
}

// ---------------------------------------------------------------------------
// Kernel 2: scatter entity indices into the inverse map.
// Handles both int64 and int32 location buffers by runtime detection:
// if int64 (little-endian, values in [0,128)), every odd int32 word is 0.
// Coordinates are ~uniform in [0,128), so 64 consecutive zero odd-words under
// an int32 layout has probability ~(1/128)^64 — effectively impossible.
__global__ void scatter_inv_kernel(const int* __restrict__ loc32) {
    __shared__ int s_is64;
    if (threadIdx.x == 0) {
        int allzero = 1;
        #pragma unroll
        for (int k = 0; k < 64; k++) allzero &= (loc32[2 * k + 1] == 0);
        s_is64 = allzero;
    }
    __syncthreads();

    int e = blockIdx.x * blockDim.x + threadIdx.x;   // entity index in [0, B*M)
    if (e >= BB * MM) return;

    int y, x;
    if (s_is64) {       // int64 layout: [y_lo, y_hi, x_lo, x_hi] per entity
        y = loc32[4 * e];
        x = loc32[4 * e + 2];
    } else {            // int32 layout: [y, x] per entity
        y = loc32[2 * e];
        x = loc32[2 * e + 1];
    }
    int b = e / MM;
    int m = e - b * MM;
    g_inv[b * HWPX + y * WPX + x] = m;
}

// ---------------------------------------------------------------------------
// Kernel 3: gather-based output construction, fully coalesced float4 stores.
// One thread owns (b, group of 4 consecutive pixels). It loads its int4 of
// inverse indices ONCE, then loops over all 128 channels, emitting one float4
// per channel. Warp-level: 32 threads x 16B = 512B contiguous store per
// channel iteration. Empty groups (88%) take a pure zero-streaming fast path.
__global__ void gather_out_kernel(const float* __restrict__ xin,
                                  float* __restrict__ out) {
    int t  = blockIdx.x * blockDim.x + threadIdx.x;  // [0, BB*HW4)
    int p4 = t & (HW4 - 1);                          // pixel-group within image
    int b  = t >> 12;                                // batch

    int4 inv4 = ((const int4*)g_inv)[b * HW4 + p4];

    float4* out4 = (float4*)out + (size_t)b * NN * HW4 + p4;
    const float4 z = make_float4(0.f, 0.f, 0.f, 0.f);

    // All four pixels empty <=> all sign bits set (entries are -1 or >= 0).
    if ((inv4.x & inv4.y & inv4.z & inv4.w) < 0) {
        #pragma unroll 8
        for (int n = 0; n < NN; n++) {
            out4[(size_t)n * HW4] = z;
        }
        return;
    }

    const float* xb = xin + (size_t)b * MM * NN;
    const float* r0 = (inv4.x >= 0) ? xb + (size_t)inv4.x * NN : nullptr;
    const float* r1 = (inv4.y >= 0) ? xb + (size_t)inv4.y * NN : nullptr;
    const float* r2 = (inv4.z >= 0) ? xb + (size_t)inv4.z * NN : nullptr;
    const float* r3 = (inv4.w >= 0) ? xb + (size_t)inv4.w * NN : nullptr;

    #pragma unroll 4
    for (int n = 0; n < NN; n++) {
        float4 v;
        v.x = r0 ? r0[n] : 0.f;
        v.y = r1 ? r1[n] : 0.f;
        v.z = r2 ? r2[n] : 0.f;
        v.w = r3 ? r3[n] : 0.f;
        out4[(size_t)n * HW4] = v;
    }
}

// ---------------------------------------------------------------------------
extern "C" void kernel_launch(void* const* d_in, const int* in_sizes, int n_in,
                              void* d_out, int out_size) {
    const float* x     = (const float*)d_in[0];
    const int*   loc32 = (const int*)d_in[1];   // raw view; width detected on device
    float*       out   = (float*)d_out;

    (void)in_sizes; (void)n_in; (void)out_size;

    // 1) inv = -1 everywhere: BB*HWPX/4 = 131072 int4 stores
    init_inv_kernel<<<512, 256>>>();

    // 2) scatter entity ids: BB*MM = 16384 threads
    scatter_inv_kernel<<<64, 256>>>(loc32);

    // 3) gather + zero-fill output: BB*HW4 = 131072 threads, 128 float4 each
    gather_out_kernel<<<512, 256>>>(x, out);
}

// round 2
// speedup vs baseline: 2.8233x; 2.8233x over previous
#include <cuda_runtime.h>
#include <stdint.h>

// Shapes (fixed):
//   x:        (B, M, N)  float32          B=32, M=512, N=128
//   location: (B, M, 2)  int64/int32 (y, x), H=W=128
//   out:      (B, N, H, W) float32
#define BB   32
#define MM   512
#define NN   128
#define WPX  128
#define HWPX 16384   // 128*128
#define HW4  4096    // HWPX/4
#define NCH  16      // channels per gather thread

// Inverse map: inv[b*HWPX + pixel] = m or -1. (2 MB)
__device__ int g_inv[BB * HWPX];
// Transposed x: xT[b][n][m]. (8 MB)
__device__ float g_xT[BB * NN * MM];

// ---------------------------------------------------------------------------
// Kernel 1: inv = -1 (int4 stores).
__global__ void init_inv_kernel() {
    int i = blockIdx.x * blockDim.x + threadIdx.x;
    ((int4*)g_inv)[i] = make_int4(-1, -1, -1, -1);
}

// ---------------------------------------------------------------------------
// Kernel 2: scatter entity indices. Detects int64 vs int32 location layout on
// device: under int64 (values < 128) every odd int32 word is 0; 64 consecutive
// zero odd-words under int32 layout has probability ~(1/128)^64.
__global__ void scatter_inv_kernel(const int* __restrict__ loc32) {
    __shared__ int s_is64;
    if (threadIdx.x == 0) {
        int allzero = 1;
        #pragma unroll
        for (int k = 0; k < 64; k++) allzero &= (loc32[2 * k + 1] == 0);
        s_is64 = allzero;
    }
    __syncthreads();

    int e = blockIdx.x * blockDim.x + threadIdx.x;   // [0, B*M)
    if (e >= BB * MM) return;

    int y, x;
    if (s_is64) { y = loc32[4 * e];  x = loc32[4 * e + 2]; }
    else        { y = loc32[2 * e];  x = loc32[2 * e + 1]; }
    int b = e / MM;
    int m = e - b * MM;
    g_inv[b * HWPX + y * WPX + x] = m;
}

// ---------------------------------------------------------------------------
// Kernel 3: transpose x (B,M,N) -> xT (B,N,M). 32x32 tiles, smem 32x33.
__global__ void transpose_x_kernel(const float* __restrict__ x) {
    __shared__ float tile[32][33];
    int b  = blockIdx.z;
    int m0 = blockIdx.x * 32;
    int n0 = blockIdx.y * 32;
    int tx = threadIdx.x, ty = threadIdx.y;   // block (32, 8)

    const float* xb  = x    + (size_t)b * MM * NN;
    float*       xTb = g_xT + (size_t)b * NN * MM;

    #pragma unroll
    for (int k = 0; k < 32; k += 8)
        tile[ty + k][tx] = xb[(size_t)(m0 + ty + k) * NN + n0 + tx];
    __syncthreads();
    #pragma unroll
    for (int k = 0; k < 32; k += 8)
        xTb[(size_t)(n0 + ty + k) * MM + m0 + tx] = tile[tx][ty + k];
}

// ---------------------------------------------------------------------------
// Kernel 4: gather + zero-fill. Thread = (b, 16-channel chunk, pixel quad).
// inv4 loaded once, reused for 16 channels. Gathers are predicated scalar
// loads from a 2 KB L1-resident row (only ~3% of lanes active per LDG).
// Stores: warp = 512 B contiguous STG.128 per channel iteration. No branches
// -> no divergence, stores stay fully coalesced.
__global__ void __launch_bounds__(256) gather_out_kernel(float* __restrict__ out) {
    int p4 = blockIdx.x * blockDim.x + threadIdx.x;  // [0, HW4)
    int b  = blockIdx.z;
    int n0 = blockIdx.y * NCH;

    int4 inv4 = ((const int4*)g_inv)[b * HW4 + p4];

    const float* xTb  = g_xT + ((size_t)b * NN + n0) * MM;
    float4*      out4 = (float4*)out + ((size_t)b * NN + n0) * HW4 + p4;

    #pragma unroll 4
    for (int j = 0; j < NCH; j++) {
        const float* row = xTb + (size_t)j * MM;
        float4 v;
        v.x = (inv4.x >= 0) ? row[inv4.x] : 0.f;
        v.y = (inv4.y >= 0) ? row[inv4.y] : 0.f;
        v.z = (inv4.z >= 0) ? row[inv4.z] : 0.f;
        v.w = (inv4.w >= 0) ? row[inv4.w] : 0.f;
        out4[(size_t)j * HW4] = v;
    }
}

// ---------------------------------------------------------------------------
extern "C" void kernel_launch(void* const* d_in, const int* in_sizes, int n_in,
                              void* d_out, int out_size) {
    const float* x     = (const float*)d_in[0];
    const int*   loc32 = (const int*)d_in[1];
    float*       out   = (float*)d_out;
    (void)in_sizes; (void)n_in; (void)out_size;

    // 1) inv = -1
    init_inv_kernel<<<512, 256>>>();
    // 2) scatter entity ids
    scatter_inv_kernel<<<64, 256>>>(loc32);
    // 3) xT = transpose(x)
    transpose_x_kernel<<<dim3(16, 4, 32), dim3(32, 8)>>>(x);
    // 4) gather + zero-fill output
    gather_out_kernel<<<dim3(16, NN / NCH, 32), 256>>>(out);
}

// round 3
// speedup vs baseline: 3.0933x; 1.0956x over previous
#include <cuda_runtime.h>
#include <stdint.h>

// Shapes (fixed):
//   x:        (B, M, N)  float32          B=32, M=512, N=128
//   location: (B, M, 2)  int64/int32 (y, x), H=W=128
//   out:      (B, N, H, W) float32
#define BB   32
#define MM   512
#define NN   128
#define WPX  128
#define HWPX 16384   // 128*128
#define HW4  4096    // HWPX/4
#define NCH  16      // channels per gather thread per block.y step

// Inverse map: inv[b*HWPX + pixel] = m or -1. (2 MB) Cleared via memset(0xFF).
__device__ int g_inv[BB * HWPX];

// ---------------------------------------------------------------------------
// Kernel 1: scatter entity indices. Detects int64 vs int32 location layout on
// device: under int64 (values < 128) every odd int32 word is 0; 64 consecutive
// zero odd-words under an int32 layout has probability ~(1/128)^64.
__global__ void scatter_inv_kernel(const int* __restrict__ loc32) {
    __shared__ int s_is64;
    if (threadIdx.x == 0) {
        int allzero = 1;
        #pragma unroll
        for (int k = 0; k < 64; k++) allzero &= (loc32[2 * k + 1] == 0);
        s_is64 = allzero;
    }
    __syncthreads();

    int e = blockIdx.x * blockDim.x + threadIdx.x;   // [0, B*M)
    if (e >= BB * MM) return;

    int y, x;
    if (s_is64) { y = loc32[4 * e];  x = loc32[4 * e + 2]; }
    else        { y = loc32[2 * e];  x = loc32[2 * e + 1]; }
    int b = e / MM;
    int m = e - b * MM;
    g_inv[b * HWPX + y * WPX + x] = m;
}

// ---------------------------------------------------------------------------
// Kernel 2: gather + zero-fill, vectorized gathers from x's NATIVE layout.
// Thread = (b, 16-channel chunk, pixel quad). For each of its 4 entity slots,
// the 16 needed channel values are a contiguous 64B run in x -> 4 predicated
// LDG.128 per slot (16 total, vs 64 scalar LDGs before). A static register
// transpose then feeds 16 fully coalesced STG.128 (warp = 512B bursts).
// Branch-free: predicated loads keep stores coalesced; ~97% of lanes are
// predicated off per gather, so gather DRAM traffic stays tiny.
__global__ void __launch_bounds__(256) gather_out_kernel(
        const float* __restrict__ xin, float* __restrict__ out) {
    int p4 = blockIdx.x * blockDim.x + threadIdx.x;  // [0, HW4)
    int b  = blockIdx.z;
    int n0 = blockIdx.y * NCH;

    int4 inv4 = ((const int4*)g_inv)[b * HW4 + p4];

    // x[b][m][n0 + 0..15] viewed as 4 float4s; row stride NN/4 = 32 float4s.
    const float4* xb = (const float4*)(xin + (size_t)b * MM * NN) + (n0 >> 2);
    const float4  z  = make_float4(0.f, 0.f, 0.f, 0.f);

    float4 e0[4], e1[4], e2[4], e3[4];
    #pragma unroll
    for (int q = 0; q < 4; q++) {
        e0[q] = (inv4.x >= 0) ? xb[(size_t)inv4.x * (NN / 4) + q] : z;
        e1[q] = (inv4.y >= 0) ? xb[(size_t)inv4.y * (NN / 4) + q] : z;
        e2[q] = (inv4.z >= 0) ? xb[(size_t)inv4.z * (NN / 4) + q] : z;
        e3[q] = (inv4.w >= 0) ? xb[(size_t)inv4.w * (NN / 4) + q] : z;
    }

    float4* out4 = (float4*)out + ((size_t)b * NN + n0) * HW4 + p4;
    #pragma unroll
    for (int q = 0; q < 4; q++) {
        float4 a = e0[q], c = e1[q], d = e2[q], f = e3[q];
        out4[(size_t)(4 * q + 0) * HW4] = make_float4(a.x, c.x, d.x, f.x);
        out4[(size_t)(4 * q + 1) * HW4] = make_float4(a.y, c.y, d.y, f.y);
        out4[(size_t)(4 * q + 2) * HW4] = make_float4(a.z, c.z, d.z, f.z);
        out4[(size_t)(4 * q + 3) * HW4] = make_float4(a.w, c.w, d.w, f.w);
    }
}

// ---------------------------------------------------------------------------
extern "C" void kernel_launch(void* const* d_in, const int* in_sizes, int n_in,
                              void* d_out, int out_size) {
    const float* x     = (const float*)d_in[0];
    const int*   loc32 = (const int*)d_in[1];
    float*       out   = (float*)d_out;
    (void)in_sizes; (void)n_in; (void)out_size;

    // 1) inv = -1 everywhere (0xFF fill). cudaMemsetAsync is graph-capturable.
    void* inv_ptr = nullptr;
    cudaGetSymbolAddress(&inv_ptr, g_inv);
    cudaMemsetAsync(inv_ptr, 0xFF, sizeof(int) * BB * HWPX, 0);

    // 2) scatter entity ids: BB*MM = 16384 threads
    scatter_inv_kernel<<<64, 256>>>(loc32);

    // 3) gather + zero-fill output: (16, 8, 32) blocks x 256 threads
    gather_out_kernel<<<dim3(HW4 / 256, NN / NCH, BB), 256>>>(x, out);
}

// round 4
// speedup vs baseline: 3.4271x; 1.1079x over previous
#include <cuda_runtime.h>
#include <stdint.h>

// Shapes (fixed):
//   x:        (B, M, N)  float32          B=32, M=512, N=128
//   location: (B, M, 2)  int64/int32 (y, x), H=W=128
//   out:      (B, N, H, W) float32
#define BB   32
#define MM   512
#define NN   128
#define WPX  128
#define HWPX 16384   // 128*128
#define HW4  4096    // HWPX/4
#define NCH  16      // channels per gather thread per block.y step

// Inverse map: inv[b*HWPX + pixel] = m or -1. (2 MB) Cleared via memset(0xFF).
__device__ int g_inv[BB * HWPX];

// ---------------------------------------------------------------------------
// Kernel 1: scatter entity indices. Detects int64 vs int32 location layout on
// device: under int64 (values < 128) every odd int32 word is 0; 64 consecutive
// zero odd-words under an int32 layout has probability ~(1/128)^64.
__global__ void scatter_inv_kernel(const int* __restrict__ loc32) {
    __shared__ int s_is64;
    if (threadIdx.x == 0) {
        int allzero = 1;
        #pragma unroll
        for (int k = 0; k < 64; k++) allzero &= (loc32[2 * k + 1] == 0);
        s_is64 = allzero;
    }
    __syncthreads();

    int e = blockIdx.x * blockDim.x + threadIdx.x;   // [0, B*M)
    if (e >= BB * MM) return;

    int y, x;
    if (s_is64) { y = loc32[4 * e];  x = loc32[4 * e + 2]; }
    else        { y = loc32[2 * e];  x = loc32[2 * e + 1]; }
    int b = e / MM;
    int m = e - b * MM;
    g_inv[b * HWPX + y * WPX + x] = m;
}

// ---------------------------------------------------------------------------
// Kernel 2: gather + zero-fill. Thread = (b, 16-channel chunk, pixel quad).
// Pipelined per q: load 4 entity float4s (predicated LDG.128.NC), register-
// transpose, 4 streaming STG.128 — only 4 float4s live at once, so regs stay
// ~30 and __launch_bounds__(256,8) gives 100% occupancy for latency hiding.
// All offsets are 32-bit (max float4 index 16.7M).
__global__ void __launch_bounds__(256, 8) gather_out_kernel(
        const float4* __restrict__ xin, float4* __restrict__ out) {
    int p4 = blockIdx.x * 256 + threadIdx.x;   // [0, HW4)
    int b  = blockIdx.z;
    int n0 = blockIdx.y * NCH;

    int4 inv4 = ((const int4*)g_inv)[b * HW4 + p4];

    // x[b][m][n0 + 0..15] = 4 float4s at row stride NN/4 = 32.
    const float4* xb = xin + b * (MM * NN / 4) + (n0 >> 2);
    float4*       o  = out + (b * NN + n0) * HW4 + p4;
    const float4  z  = make_float4(0.f, 0.f, 0.f, 0.f);

    bool v0 = inv4.x >= 0, v1 = inv4.y >= 0, v2 = inv4.z >= 0, v3 = inv4.w >= 0;
    int  i0 = inv4.x * (NN / 4), i1 = inv4.y * (NN / 4);
    int  i2 = inv4.z * (NN / 4), i3 = inv4.w * (NN / 4);

    #pragma unroll
    for (int q = 0; q < 4; q++) {
        float4 a = v0 ? __ldg(xb + i0 + q) : z;
        float4 c = v1 ? __ldg(xb + i1 + q) : z;
        float4 d = v2 ? __ldg(xb + i2 + q) : z;
        float4 f = v3 ? __ldg(xb + i3 + q) : z;

        __stcs(o + (4 * q + 0) * HW4, make_float4(a.x, c.x, d.x, f.x));
        __stcs(o + (4 * q + 1) * HW4, make_float4(a.y, c.y, d.y, f.y));
        __stcs(o + (4 * q + 2) * HW4, make_float4(a.z, c.z, d.z, f.z));
        __stcs(o + (4 * q + 3) * HW4, make_float4(a.w, c.w, d.w, f.w));
    }
}

// ---------------------------------------------------------------------------
extern "C" void kernel_launch(void* const* d_in, const int* in_sizes, int n_in,
                              void* d_out, int out_size) {
    const float* x     = (const float*)d_in[0];
    const int*   loc32 = (const int*)d_in[1];
    float*       out   = (float*)d_out;
    (void)in_sizes; (void)n_in; (void)out_size;

    // 1) inv = -1 everywhere (0xFF fill). Graph-capturable memset node.
    void* inv_ptr = nullptr;
    cudaGetSymbolAddress(&inv_ptr, g_inv);
    cudaMemsetAsync(inv_ptr, 0xFF, sizeof(int) * BB * HWPX, 0);

    // 2) scatter entity ids: BB*MM = 16384 threads
    scatter_inv_kernel<<<64, 256>>>(loc32);

    // 3) gather + zero-fill output: (16, 8, 32) blocks x 256 threads
    gather_out_kernel<<<dim3(HW4 / 256, NN / NCH, BB), 256>>>(
        (const float4*)x, (float4*)out);
}